// round 11
// baseline (speedup 1.0000x reference)
#include <cuda_runtime.h>

#define HID 128
#define INP 33
#define OUTD 3
#define TT 2000
#define BATCH 256

typedef unsigned long long u64;

// Packed fp32x2 FMA (FFMA2) — only reachable via PTX fma.rn.f32x2.
__device__ __forceinline__ u64 ffma2(u64 a, u64 b, u64 c) {
    u64 d;
    asm("fma.rn.f32x2 %0, %1, %2, %3;" : "=l"(d) : "l"(a), "l"(b), "l"(c));
    return d;
}
__device__ __forceinline__ float2 unpack2(u64 v) {
    float2 f;
    asm("mov.b64 {%0, %1}, %2;" : "=f"(f.x), "=f"(f.y) : "l"(v));
    return f;
}
__device__ __forceinline__ u64 pack2(float x, float y) {
    u64 v;
    asm("mov.b64 %0, {%1, %2};" : "=l"(v) : "f"(x), "f"(y));
    return v;
}

// Accurate tanh via __expf (MUFU): rel err ~1e-6 (tanh.approx's 6e-4 is unsafe
// for a 2000-step recurrence).
__device__ __forceinline__ float fast_tanh(float x) {
    float ax = fabsf(x);
    float e = __expf(2.0f * fminf(ax, 10.0f));
    float t = 1.0f - 2.0f / (e + 1.0f);
    return copysignf(t, x);
}

// ---------------------------------------------------------------------------
// Pass 1: input projection, in-place into the hidden output buffer.
// Grid-stride persistent CTAs (kills the 32000-CTA wave churn of R5).
// 256 threads: thread j = tid&127 holds W_in row j; half 0 does rows 0-15 of
// each 32-row tile, half 1 rows 16-31. x staged in smem padded to 34 floats
// per row so packed pairs are 8B-aligned (pad multiplies by zero).
// ---------------------------------------------------------------------------
#define PR 32

__global__ void __launch_bounds__(256)
proj_kernel(const float* __restrict__ x,
            const float* __restrict__ W_in,
            const float* __restrict__ b_in,
            float* __restrict__ proj)
{
    __shared__ __align__(16) float xs[PR][34];

    const int tid  = threadIdx.x;
    const int j    = tid & 127;
    const int half = tid >> 7;

    // W_in row j -> 17 packed pairs (last = (w32, 0))
    u64 wi[17];
    {
        float wv[34];
        #pragma unroll
        for (int i = 0; i < INP; i++) wv[i] = W_in[j * INP + i];
        wv[33] = 0.0f;
        #pragma unroll
        for (int i = 0; i < 17; i++) wi[i] = pack2(wv[2 * i], wv[2 * i + 1]);
    }
    const float bj = b_in[j];

    if (tid < PR) xs[tid][33] = 0.0f;   // pad column, written once

    const int ntiles = (BATCH * TT) / PR;   // 16000
    for (int tile = blockIdx.x; tile < ntiles; tile += gridDim.x) {
        const long base = (long)tile * PR;
        __syncthreads();                     // xs free from previous tile
        const float* xsrc = x + base * INP;
        for (int idx = tid; idx < PR * INP; idx += 256) {
            int r = idx / INP, i = idx - r * INP;
            xs[r][i] = xsrc[idx];
        }
        __syncthreads();

        #pragma unroll 4
        for (int rr = 0; rr < 16; rr++) {
            int r = half * 16 + rr;
            const u64* xp = (const u64*)xs[r];
            u64 acc[4] = {0ull, 0ull, 0ull, 0ull};
            #pragma unroll
            for (int i = 0; i < 17; i++)
                acc[i & 3] = ffma2(wi[i], xp[i], acc[i & 3]);
            float2 f0 = unpack2(acc[0]), f1 = unpack2(acc[1]);
            float2 f2 = unpack2(acc[2]), f3 = unpack2(acc[3]);
            float s = ((f0.x + f1.x) + (f2.x + f3.x))
                    + ((f0.y + f1.y) + (f2.y + f3.y)) + bj;
            proj[(base + r) * HID + j] = s;   // coalesced per warp-group
        }
    }
}

// ---------------------------------------------------------------------------
// Pass 2: serial recurrence — TWO batch rows per thread (128 CTAs, one per
// SM). W_rec row j is SHARED by both rows -> still 128 weight regs (~190
// total; launch_bounds(128,1) gives ptxas the full 255 budget so nothing
// spills). The two rows' FFMA2/reduce/tanh chains are independent, so each
// row's serial latency tail hides under the other's issue slots. One barrier
// per step (4 warps); gmem h-stores issued AFTER the barrier
// (deferred-blocking BAR lets them overlap the next step's LDS ramp).
// ---------------------------------------------------------------------------
__global__ void __launch_bounds__(128, 1)
rnn_recurrence_kernel(const float* __restrict__ W_rec,
                      float* __restrict__ hidden /* in: proj, out: h */)
{
    __shared__ __align__(16) float hA[2][HID];
    __shared__ __align__(16) float hB[2][HID];

    const int j = threadIdx.x;
    const int b0 = blockIdx.x * 2;

    u64 w[64];
    {
        const ulonglong2* wrow = (const ulonglong2*)(W_rec + j * HID);
        #pragma unroll
        for (int k = 0; k < 32; k++) {
            ulonglong2 v = wrow[k];
            w[2 * k]     = v.x;
            w[2 * k + 1] = v.y;
        }
    }

    hA[0][j] = 0.0f;
    hB[0][j] = 0.0f;
    float hjA = 0.0f, hjB = 0.0f;
    float* pA = hidden + (size_t)b0 * TT * HID + j;
    float* pB = pA + (size_t)TT * HID;

    float aCur = __ldg(pA), aNxt = __ldg(pA + HID);
    float bCur = __ldg(pB), bNxt = __ldg(pB + HID);
    __syncthreads();

    int p = 0;
    for (int t = 0; t < TT; t++) {
        float aFut = 0.0f, bFut = 0.0f;
        if (t + 2 < TT) {
            aFut = __ldg(pA + (size_t)(t + 2) * HID);
            bFut = __ldg(pB + (size_t)(t + 2) * HID);
        }

        const ulonglong2* ha = (const ulonglong2*)hA[p];
        const ulonglong2* hb = (const ulonglong2*)hB[p];
        u64 accA[4] = {pack2(aCur, 0.0f), 0ull, 0ull, 0ull};
        u64 accB[4] = {pack2(bCur, 0.0f), 0ull, 0ull, 0ull};

        #pragma unroll
        for (int k = 0; k < 32; k++) {
            ulonglong2 va = ha[k];                       // broadcast LDS.128
            ulonglong2 vb = hb[k];
            accA[(2 * k)     & 3] = ffma2(w[2 * k],     va.x, accA[(2 * k)     & 3]);
            accA[(2 * k + 1) & 3] = ffma2(w[2 * k + 1], va.y, accA[(2 * k + 1) & 3]);
            accB[(2 * k)     & 3] = ffma2(w[2 * k],     vb.x, accB[(2 * k)     & 3]);
            accB[(2 * k + 1) & 3] = ffma2(w[2 * k + 1], vb.y, accB[(2 * k + 1) & 3]);
        }

        float2 a0 = unpack2(accA[0]), a1 = unpack2(accA[1]);
        float2 a2 = unpack2(accA[2]), a3 = unpack2(accA[3]);
        float preA = ((a0.x + a1.x) + (a2.x + a3.x))
                   + ((a0.y + a1.y) + (a2.y + a3.y));
        float2 c0 = unpack2(accB[0]), c1 = unpack2(accB[1]);
        float2 c2 = unpack2(accB[2]), c3 = unpack2(accB[3]);
        float preB = ((c0.x + c1.x) + (c2.x + c3.x))
                   + ((c0.y + c1.y) + (c2.y + c3.y));

        float hnA = 0.96f * hjA + 0.04f * fast_tanh(preA);
        float hnB = 0.96f * hjB + 0.04f * fast_tanh(preB);

        hA[p ^ 1][j] = hnA;
        hB[p ^ 1][j] = hnB;
        __syncthreads();                 // deferred-blocking: stores below overlap

        pA[(size_t)t * HID] = hnA;       // coalesced 512B stores
        pB[(size_t)t * HID] = hnB;

        hjA = hnA; hjB = hnB;
        aCur = aNxt; aNxt = aFut;
        bCur = bNxt; bNxt = bFut;
        p ^= 1;
    }
}

// ---------------------------------------------------------------------------
// Pass 3: readout. 4 rows per warp (12 interleaved butterfly chains hide SHFL
// latency), grid-stride, lane 0 writes 12 contiguous floats as 3 STG.128.
// ---------------------------------------------------------------------------
__global__ void __launch_bounds__(256)
readout_kernel(const float* __restrict__ hidden,
               const float* __restrict__ W_out,
               const float* __restrict__ b_out,
               float* __restrict__ pred,
               int nrows)
{
    const int lane   = threadIdx.x & 31;
    const int gwarp  = (blockIdx.x * blockDim.x + threadIdx.x) >> 5;
    const int nwarps = (gridDim.x * blockDim.x) >> 5;

    const float4* w4 = (const float4*)W_out;
    float4 w0 = __ldg(&w4[lane]);
    float4 w1 = __ldg(&w4[32 + lane]);
    float4 w2 = __ldg(&w4[64 + lane]);
    float bo0 = __ldg(&b_out[0]), bo1 = __ldg(&b_out[1]), bo2 = __ldg(&b_out[2]);

    for (int r0 = gwarp * 4; r0 < nrows; r0 += nwarps * 4) {
        float p[4][3];
        #pragma unroll
        for (int rr = 0; rr < 4; rr++) {
            const float4* h4 = (const float4*)(hidden + (size_t)(r0 + rr) * HID);
            float4 hv = h4[lane];
            p[rr][0] = hv.x * w0.x + hv.y * w0.y + hv.z * w0.z + hv.w * w0.w;
            p[rr][1] = hv.x * w1.x + hv.y * w1.y + hv.z * w1.z + hv.w * w1.w;
            p[rr][2] = hv.x * w2.x + hv.y * w2.y + hv.z * w2.z + hv.w * w2.w;
        }
        #pragma unroll
        for (int off = 16; off > 0; off >>= 1) {
            #pragma unroll
            for (int rr = 0; rr < 4; rr++) {
                p[rr][0] += __shfl_xor_sync(0xFFFFFFFFu, p[rr][0], off);
                p[rr][1] += __shfl_xor_sync(0xFFFFFFFFu, p[rr][1], off);
                p[rr][2] += __shfl_xor_sync(0xFFFFFFFFu, p[rr][2], off);
            }
        }
        if (lane == 0) {
            float4* o = (float4*)(pred + (size_t)r0 * OUTD);  // r0%4==0 -> 16B aligned
            o[0] = make_float4(p[0][0] + bo0, p[0][1] + bo1, p[0][2] + bo2, p[1][0] + bo0);
            o[1] = make_float4(p[1][1] + bo1, p[1][2] + bo2, p[2][0] + bo0, p[2][1] + bo1);
            o[2] = make_float4(p[2][2] + bo2, p[3][0] + bo0, p[3][1] + bo1, p[3][2] + bo2);
        }
    }
}

extern "C" void kernel_launch(void* const* d_in, const int* in_sizes, int n_in,
                              void* d_out, int out_size)
{
    const float* x     = (const float*)d_in[0];  // [B,T,33]
    const float* W_in  = (const float*)d_in[1];  // [128,33]
    const float* b_in  = (const float*)d_in[2];  // [128]
    const float* W_rec = (const float*)d_in[3];  // [128,128]
    const float* W_out = (const float*)d_in[4];  // [3,128]
    const float* b_out = (const float*)d_in[5];  // [3]

    float* out    = (float*)d_out;
    float* pred   = out;                               // [B,T,3]
    float* hidden = out + (size_t)BATCH * TT * OUTD;   // [B,T,128]; proj then h

    // Pass 1: proj -> hidden (in place), persistent grid
    proj_kernel<<<456, 256>>>(x, W_in, b_in, hidden);

    // Pass 2: serial recurrence, 2 batch rows per thread (one CTA per SM)
    rnn_recurrence_kernel<<<BATCH / 2, 128>>>(W_rec, hidden);

    // Pass 3: readout, persistent grid
    int nrows = BATCH * TT;                            // 512000
    readout_kernel<<<608, 256>>>(hidden, W_out, b_out, pred, nrows);
}